// round 5
// baseline (speedup 1.0000x reference)
#include <cuda_runtime.h>
#include <cuda_bf16.h>
#include <cstdint>

#define NN 50000
#define NE 3200000
#define TILE_M 128
#define N_TILES (NE / TILE_M)   // 25000 exact

// ---------------- scratch (static __device__ — no allocations) ----------------
__device__ int g_deg[NN];
__device__ int g_row_start[NN + 1];
__device__ int g_cursor[NN];
__device__ int g_src_sorted[NE];
__device__ int g_dst_sorted[NE];
__device__ int g_eperm[NE];
__device__ __align__(16) float g_edge_part[(size_t)NE * 64];   // 819 MB, sorted-by-dst
__device__ __align__(16) float g_np[(size_t)NN * 64];
__device__ __align__(16) float g_aggr[(size_t)NN * 64];
__device__ __align__(16) float g_xA[NN * 8];
__device__ __align__(16) float g_xB[NN * 8];

// ---------------- preprocessing: CSR sort by dst ----------------
__global__ void k_zero_deg() {
    int i = blockIdx.x * blockDim.x + threadIdx.x;
    if (i < NN) g_deg[i] = 0;
}
__global__ void k_hist(const int* __restrict__ ei) {
    int e = blockIdx.x * blockDim.x + threadIdx.x;
    if (e < NE) atomicAdd(&g_deg[ei[NE + e]], 1);
}
__global__ void k_scan() {
    __shared__ int sm[1024];
    __shared__ int carry;
    if (threadIdx.x == 0) carry = 0;
    __syncthreads();
    for (int base = 0; base < NN; base += 1024) {
        int i = base + threadIdx.x;
        int v = (i < NN) ? g_deg[i] : 0;
        sm[threadIdx.x] = v;
        __syncthreads();
        for (int off = 1; off < 1024; off <<= 1) {
            int t = (threadIdx.x >= off) ? sm[threadIdx.x - off] : 0;
            __syncthreads();
            sm[threadIdx.x] += t;
            __syncthreads();
        }
        if (i < NN) {
            int excl = carry + sm[threadIdx.x] - v;
            g_row_start[i] = excl;
            g_cursor[i]    = excl;
        }
        __syncthreads();
        if (threadIdx.x == 0) carry += sm[1023];
        __syncthreads();
    }
    if (threadIdx.x == 0) g_row_start[NN] = NE;
}
__global__ void k_scatter(const int* __restrict__ ei) {
    int e = blockIdx.x * blockDim.x + threadIdx.x;
    if (e < NE) {
        int d = ei[NE + e];
        int pos = atomicAdd(&g_cursor[d], 1);
        g_src_sorted[pos] = ei[e];
        g_dst_sorted[pos] = d;
        g_eperm[pos] = e;
    }
}
__global__ void k_edge_part(const float* __restrict__ ea,
                            const float* __restrict__ w1_0,
                            const float* __restrict__ b1_0) {
    __shared__ float Ws[5 * 64];
    __shared__ float Bs[64];
    int tid = threadIdx.x;
    for (int i = tid; i < 320; i += blockDim.x) Ws[i] = w1_0[512 + i];
    if (tid < 64) Bs[tid] = b1_0[tid];
    __syncthreads();
    long long idx = (long long)blockIdx.x * blockDim.x + tid;
    if (idx >= (long long)NE * 64) return;
    int pos = (int)(idx >> 6);
    int j   = (int)(idx & 63);
    int e   = g_eperm[pos];
    const float* a = ea + (long long)e * 5;
    float s = Bs[j];
    s += a[0] * Ws[0 * 64 + j];
    s += a[1] * Ws[1 * 64 + j];
    s += a[2] * Ws[2 * 64 + j];
    s += a[3] * Ws[3 * 64 + j];
    s += a[4] * Ws[4 * 64 + j];
    g_edge_part[idx] = s;
}

// ---------------- per-iteration kernels ----------------
__global__ void k_node_part(const float* __restrict__ x, const float* __restrict__ w1_0) {
    __shared__ float Ws[512];
    int tid = threadIdx.x;
    if (tid < 512) Ws[tid] = w1_0[tid];
    __syncthreads();
    int idx = blockIdx.x * blockDim.x + tid;
    if (idx >= NN * 64) return;
    int n = idx >> 6, j = idx & 63;
    const float* xr = x + n * 8;
    float s = xr[0] * Ws[j]        + xr[1] * Ws[64 + j]
            + xr[2] * Ws[128 + j]  + xr[3] * Ws[192 + j]
            + xr[4] * Ws[256 + j]  + xr[5] * Ws[320 + j]
            + xr[6] * Ws[384 + j]  + xr[7] * Ws[448 + j];
    g_np[idx] = s;
}

__global__ void k_zero_aggr() {
    int i = blockIdx.x * blockDim.x + threadIdx.x;
    if (i < NN * 16) ((float4*)g_aggr)[i] = make_float4(0.f, 0.f, 0.f, 0.f);
}

// ---------------- hot kernel: mma.sync bf16 split-GEMM + segmented-max ----------------
// SMEM (dynamic, bytes):
//   A_HI @ 0      128 x 72(pitch) bf16 = 18432
//   A_LO @ 18432  18432
//   OUT  @ 0      128 x 66 f32 = 33792   (overlays A after MMA phase)
//   W_HI @ 36864  64 x 72 bf16 = 9216
//   W_LO @ 46080  9216
//   BIAS @ 55296  64 f32
//   SRC  @ 55552  128 i32
//   DST  @ 56064  128 i32
#define APITCH 72
#define OPITCH 66
#define OFF_ALO  18432
#define OFF_WHI  36864
#define OFF_WLO  46080
#define OFF_BIAS 55296
#define OFF_SRC  55552
#define OFF_DST  56064
#define SMEM_BYTES 56576

__device__ __forceinline__ void mma_bf16(float* d, uint32_t a0, uint32_t a1,
                                         uint32_t a2, uint32_t a3,
                                         uint32_t b0, uint32_t b1) {
    asm volatile(
        "mma.sync.aligned.m16n8k16.row.col.f32.bf16.bf16.f32 "
        "{%0,%1,%2,%3}, {%4,%5,%6,%7}, {%8,%9}, {%0,%1,%2,%3};"
        : "+f"(d[0]), "+f"(d[1]), "+f"(d[2]), "+f"(d[3])
        : "r"(a0), "r"(a1), "r"(a2), "r"(a3), "r"(b0), "r"(b1));
}

__device__ __forceinline__ uint32_t pack_hi(float x, float y, uint32_t& lo) {
    __nv_bfloat162 h, l;
    h.x = __float2bfloat16_rn(x);
    h.y = __float2bfloat16_rn(y);
    l.x = __float2bfloat16_rn(x - __bfloat162float(h.x));
    l.y = __float2bfloat16_rn(y - __bfloat162float(h.y));
    lo = *(uint32_t*)&l;
    return *(uint32_t*)&h;
}

__global__ void __launch_bounds__(128, 3) k_edge_mma(const float* __restrict__ w1_1,
                                                     const float* __restrict__ b1_1) {
    extern __shared__ char smem[];
    const int tid = threadIdx.x;
    const int wid = tid >> 5;
    const int lane = tid & 31;
    const int g = lane >> 2;          // groupID
    const int cc = (lane & 3) * 2;    // k/col pair base

    uint32_t* AHI = (uint32_t*)smem;
    uint32_t* ALO = (uint32_t*)(smem + OFF_ALO);
    uint32_t* WHI = (uint32_t*)(smem + OFF_WHI);
    uint32_t* WLO = (uint32_t*)(smem + OFF_WLO);
    float*    OUT = (float*)smem;
    float*    bias = (float*)(smem + OFF_BIAS);
    int*      ssrc = (int*)(smem + OFF_SRC);
    int*      sdst = (int*)(smem + OFF_DST);

    // W split (once per CTA): Wsm[n][k] = w1_1[k*64 + n]
    for (int i = tid * 2; i < 4096; i += 256) {
        int n = i >> 6, k = i & 63;
        float w0 = w1_1[k * 64 + n];
        float w1 = w1_1[(k + 1) * 64 + n];
        uint32_t lo, hi = pack_hi(w0, w1, lo);
        WHI[(n * APITCH + k) >> 1] = hi;
        WLO[(n * APITCH + k) >> 1] = lo;
    }
    if (tid < 64) bias[tid] = b1_1[tid];

    // preload this lane's bias columns: per n-tile j, cols j*8+cc, +1
    float breg[8][2];
#pragma unroll
    for (int j = 0; j < 8; j++) {
        breg[j][0] = b1_1[j * 8 + cc];
        breg[j][1] = b1_1[j * 8 + cc + 1];
    }
    __syncthreads();

    for (int t = blockIdx.x; t < N_TILES; t += gridDim.x) {
        const size_t e0 = (size_t)t * TILE_M;
        ssrc[tid] = g_src_sorted[e0 + tid];
        sdst[tid] = g_dst_sorted[e0 + tid];
        __syncthreads();

        // Build A = relu(np[src] + edge_part) → bf16 hi/lo
#pragma unroll 4
        for (int p = 0; p < 32; p++) {
            int idx2 = p * 256 + tid * 2;
            int r = idx2 >> 6, c = idx2 & 63;
            float2 np = *(const float2*)(g_np + (size_t)ssrc[r] * 64 + c);
            float2 ep = *(const float2*)(g_edge_part + e0 * 64 + idx2);
            float h0 = fmaxf(np.x + ep.x, 0.f);
            float h1 = fmaxf(np.y + ep.y, 0.f);
            uint32_t lo, hi = pack_hi(h0, h1, lo);
            AHI[(r * APITCH + c) >> 1] = hi;
            ALO[(r * APITCH + c) >> 1] = lo;
        }
        __syncthreads();

        // MMA: rows [wid*32, wid*32+32) = 2 m16 tiles x 8 n8 tiles, k=64
        float acc[2][8][4];
#pragma unroll
        for (int mt = 0; mt < 2; mt++)
#pragma unroll
            for (int j = 0; j < 8; j++)
#pragma unroll
                for (int q = 0; q < 4; q++) acc[mt][j][q] = 0.f;

#pragma unroll
        for (int s = 0; s < 3; s++) {
            uint32_t* Ab = (s == 2) ? ALO : AHI;   // hi*hi, hi*lo, lo*hi
            uint32_t* Wb = (s == 1) ? WLO : WHI;
#pragma unroll
            for (int kk = 0; kk < 4; kk++) {
                int kc = cc + kk * 16;
                uint32_t a[2][4];
#pragma unroll
                for (int mt = 0; mt < 2; mt++) {
                    int r0 = wid * 32 + mt * 16 + g;
                    a[mt][0] = Ab[(r0 * APITCH + kc) >> 1];
                    a[mt][1] = Ab[((r0 + 8) * APITCH + kc) >> 1];
                    a[mt][2] = Ab[(r0 * APITCH + kc + 8) >> 1];
                    a[mt][3] = Ab[((r0 + 8) * APITCH + kc + 8) >> 1];
                }
#pragma unroll
                for (int j = 0; j < 8; j++) {
                    int n = j * 8 + g;
                    uint32_t b0 = Wb[(n * APITCH + kc) >> 1];
                    uint32_t b1 = Wb[(n * APITCH + kc + 8) >> 1];
                    mma_bf16(acc[0][j], a[0][0], a[0][1], a[0][2], a[0][3], b0, b1);
                    mma_bf16(acc[1][j], a[1][0], a[1][1], a[1][2], a[1][3], b0, b1);
                }
            }
        }
        __syncthreads();   // all warps done reading A → safe to overlay OUT

        // Store bias+relu'd msg to OUT (overlays A area)
#pragma unroll
        for (int mt = 0; mt < 2; mt++) {
            int r0 = wid * 32 + mt * 16 + g;
#pragma unroll
            for (int j = 0; j < 8; j++) {
                int cb = j * 8 + cc;
                float v0 = fmaxf(acc[mt][j][0] + breg[j][0], 0.f);
                float v1 = fmaxf(acc[mt][j][1] + breg[j][1], 0.f);
                float v2 = fmaxf(acc[mt][j][2] + breg[j][0], 0.f);
                float v3 = fmaxf(acc[mt][j][3] + breg[j][1], 0.f);
                *(float2*)(OUT + r0 * OPITCH + cb) = make_float2(v0, v1);
                *(float2*)(OUT + (r0 + 8) * OPITCH + cb) = make_float2(v2, v3);
            }
        }
        __syncthreads();

        // Epilogue: dst-keyed segmented max over warp rows, tails atomicMax
        {
            const int r = wid * 32 + lane;
            const int d = sdst[r];
            int dnext = __shfl_down_sync(0xffffffffu, d, 1);
            bool tail = (lane == 31) || (dnext != d);
#pragma unroll
            for (int ch = 0; ch < 2; ch++) {
                float v[32];
#pragma unroll
                for (int j = 0; j < 32; j++)
                    v[j] = OUT[r * OPITCH + ch * 32 + j];
#pragma unroll
                for (int off = 1; off < 32; off <<= 1) {
                    int d2 = __shfl_up_sync(0xffffffffu, d, off);
                    bool ok = (lane >= off) && (d2 == d);
#pragma unroll
                    for (int j = 0; j < 32; j++) {
                        float u = __shfl_up_sync(0xffffffffu, v[j], off);
                        if (ok) v[j] = fmaxf(v[j], u);
                    }
                }
                if (tail) {
                    int* dstp = (int*)(g_aggr + (size_t)d * 64 + ch * 32);
#pragma unroll
                    for (int j = 0; j < 32; j++)
                        atomicMax(dstp + j, __float_as_int(v[j]));
                }
            }
        }
        __syncthreads();   // protect ssrc/sdst/OUT before next tile
    }
}

// ---------------- node update (MLP2 + normalize + assemble) ----------------
__global__ void __launch_bounds__(128) k_node_update(
    const float* __restrict__ x, float* __restrict__ xout,
    const float* __restrict__ w2_0, const float* __restrict__ b2_0,
    const float* __restrict__ w2_1, const float* __restrict__ b2_1) {
    __shared__ float W0[72 * 32];
    __shared__ float B0[32];
    __shared__ float W1[160];
    __shared__ float B1[8];
    int tid = threadIdx.x;
    for (int i = tid; i < 2304; i += 128) W0[i] = w2_0[i];
    if (tid < 32) B0[tid] = b2_0[tid];
    for (int i = tid; i < 160; i += 128) W1[i] = w2_1[i];
    if (tid < 5) B1[tid] = b2_1[tid];
    __syncthreads();
    int n = blockIdx.x * 128 + tid;
    if (n >= NN) return;

    float cat[72];
#pragma unroll
    for (int k = 0; k < 8; k++) cat[k] = x[n * 8 + k];
    const float4* ag = (const float4*)(g_aggr + (size_t)n * 64);
#pragma unroll
    for (int k = 0; k < 16; k++) {
        float4 v = ag[k];
        cat[8 + 4 * k] = v.x; cat[9 + 4 * k] = v.y;
        cat[10 + 4 * k] = v.z; cat[11 + 4 * k] = v.w;
    }
    float h2[32];
#pragma unroll
    for (int j = 0; j < 32; j++) h2[j] = B0[j];
#pragma unroll 8
    for (int k = 0; k < 72; k++) {
        float c = cat[k];
#pragma unroll
        for (int j = 0; j < 32; j++) h2[j] += c * W0[k * 32 + j];
    }
#pragma unroll
    for (int j = 0; j < 32; j++) h2[j] = fmaxf(h2[j], 0.f);
    float c0 = B1[0], c1 = B1[1], c2 = B1[2], c3 = B1[3], c4 = B1[4];
#pragma unroll
    for (int k = 0; k < 32; k++) {
        float hv = h2[k];
        c0 += hv * W1[k * 5 + 0];
        c1 += hv * W1[k * 5 + 1];
        c2 += hv * W1[k * 5 + 2];
        c3 += hv * W1[k * 5 + 3];
        c4 += hv * W1[k * 5 + 4];
    }
    float nor = sqrtf(c1 * c1 + c2 * c2 + c3 * c3 + c4 * c4);
    float inv = 1.0f / fmaxf(1.0f, nor);
    float* o = xout + n * 8;
    o[0] = c0;
    o[1] = c1 * inv; o[2] = c2 * inv; o[3] = c3 * inv; o[4] = c4 * inv;
    o[5] = cat[0]; o[6] = cat[1]; o[7] = cat[2];
}

// ---------------- launch ----------------
extern "C" void kernel_launch(void* const* d_in, const int* in_sizes, int n_in,
                              void* d_out, int out_size) {
    const float* x         = (const float*)d_in[0];
    const float* edge_attr = (const float*)d_in[1];
    const int*   ei        = (const int*)d_in[2];   // JAX default: int32
    const float* w1_0      = (const float*)d_in[3];
    const float* b1_0      = (const float*)d_in[4];
    const float* w1_1      = (const float*)d_in[5];
    const float* b1_1      = (const float*)d_in[6];
    const float* w2_0      = (const float*)d_in[7];
    const float* b2_0      = (const float*)d_in[8];
    const float* w2_1      = (const float*)d_in[9];
    const float* b2_1      = (const float*)d_in[10];

    cudaFuncSetAttribute(k_edge_mma, cudaFuncAttributeMaxDynamicSharedMemorySize, SMEM_BYTES);

    // Preprocessing (edge CSR + iteration-invariant edge MLP input part)
    k_zero_deg<<<(NN + 255) / 256, 256>>>();
    k_hist<<<(NE + 255) / 256, 256>>>(ei);
    k_scan<<<1, 1024>>>();
    k_scatter<<<(NE + 255) / 256, 256>>>(ei);
    {
        long long tot = (long long)NE * 64;
        int blocks = (int)((tot + 255) / 256);
        k_edge_part<<<blocks, 256>>>(edge_attr, w1_0, b1_0);
    }

    float *xA = nullptr, *xB = nullptr;
    cudaGetSymbolAddress((void**)&xA, g_xA);
    cudaGetSymbolAddress((void**)&xB, g_xB);

    const float* cur = x;
    for (int it = 0; it < 8; it++) {
        k_node_part<<<(NN * 64 + 511) / 512, 512>>>(cur, w1_0);
        k_zero_aggr<<<(NN * 16 + 255) / 256, 256>>>();
        k_edge_mma<<<592, 128, SMEM_BYTES>>>(w1_1, b1_1);
        float* nxt = (it == 7) ? (float*)d_out : ((it & 1) ? xB : xA);
        k_node_update<<<(NN + 127) / 128, 128>>>(cur, nxt, w2_0, b2_0, w2_1, b2_1);
        cur = nxt;
    }
}